// round 10
// baseline (speedup 1.0000x reference)
#include <cuda_runtime.h>
#include <cuda_fp16.h>

// CapsuleLayer dynamic routing, GB300 sm_103a.
// B=64, I=2048, Din=16, J=32, D=32, 3 routing iters.
//
// uhat: per-i GEMM (M=1024, N=64, K=16) on HMMA (mma.sync.m16n8k16 f16->f32),
// W/x staged fp16 in smem (48B row stride: conflict-free ldmatrix), results
// packed f16x2 and transposed via stmatrix.x2.trans -> coalesced STG.128 into
// g_U[b][i][j*32+d] (same layout the routes consume).
// Routes: 5-stage block-wide cp.async ring (round-9 proven, unchanged).

#define BB 64
#define II 2048
#define CC 16
#define JJ 32
#define DD 32
#define NTILE 16   // i-tiles (blocks) per b; block covers 128 i
#define NSTAGE 5   // cp.async ring stages (8 i = 16KB per stage)
#define NITER 16   // stages per block (128 i / 8)

typedef unsigned long long u64;
typedef unsigned int u32;

__device__ __half g_U[(size_t)BB * II * JJ * DD];   // 256 MB scratch (fp16)
__device__ float g_osum[BB * JJ * DD];              // running output sum
__device__ float g_spart[NTILE][BB * JJ * DD];      // per-itile partial s

// ---------- cp.async helpers ----------
__device__ __forceinline__ void cpasync16(unsigned smem_addr, const void* g) {
    asm volatile("cp.async.cg.shared.global [%0], [%1], 16;" ::"r"(smem_addr),
                 "l"(g));
}
__device__ __forceinline__ void cpcommit() {
    asm volatile("cp.async.commit_group;");
}
template <int N>
__device__ __forceinline__ void cpwait() {
    asm volatile("cp.async.wait_group %0;" ::"n"(N));
}

// ---------- mma helpers ----------
__device__ __forceinline__ void ldmx4(u32& a0, u32& a1, u32& a2, u32& a3,
                                      u32 addr) {
    asm volatile("ldmatrix.sync.aligned.m8n8.x4.shared.b16 {%0,%1,%2,%3}, [%4];"
                 : "=r"(a0), "=r"(a1), "=r"(a2), "=r"(a3)
                 : "r"(addr));
}
__device__ __forceinline__ void ldmx2(u32& b0, u32& b1, u32 addr) {
    asm volatile("ldmatrix.sync.aligned.m8n8.x2.shared.b16 {%0,%1}, [%2];"
                 : "=r"(b0), "=r"(b1)
                 : "r"(addr));
}
__device__ __forceinline__ void stmx2t(u32 addr, u32 h0, u32 h1) {
    asm volatile("stmatrix.sync.aligned.m8n8.x2.trans.shared.b16 [%0], {%1,%2};"
                 ::"r"(addr), "r"(h0), "r"(h1));
}
__device__ __forceinline__ void mma16816(float& d0, float& d1, float& d2,
                                         float& d3, u32 a0, u32 a1, u32 a2,
                                         u32 a3, u32 b0, u32 b1) {
    const float z = 0.f;
    asm volatile(
        "mma.sync.aligned.m16n8k16.row.col.f32.f16.f16.f32 "
        "{%0,%1,%2,%3}, {%4,%5,%6,%7}, {%8,%9}, {%10,%11,%12,%13};"
        : "=f"(d0), "=f"(d1), "=f"(d2), "=f"(d3)
        : "r"(a0), "r"(a1), "r"(a2), "r"(a3), "r"(b0), "r"(b1), "f"(z), "f"(z),
          "f"(z), "f"(z));
}
__device__ __forceinline__ u32 cvtpack(float lo, float hi) {
    u32 h;
    asm("cvt.rn.f16x2.f32 %0, %1, %2;" : "=r"(h) : "f"(hi), "f"(lo));
    return h;
}

// smem layout for uhat (bytes)
#define SW_OFF 0                 // W fp16 [1024 rows][48B stride] (32B payload)
#define SX_OFF 49152             // x fp16 [64 rows][48B stride]
#define STG_OFF 52224            // per-warp staging [64 b][48B stride]
#define STG_WARP 3072
#define UHAT_SMEM (STG_OFF + 8 * STG_WARP)  // 76800

// ---------------------------------------------------------------------------
// Kernel A (HMMA): u_hat[b][i][row] = sum_c W[j][i][d][c] * x[b][i][c], fp16,
// row = j*32+d. One block per i, 8 warps; warp w owns row-tiles w*8..w*8+7.
// ---------------------------------------------------------------------------
__global__ void __launch_bounds__(256, 2)
uhat_kernel(const float* __restrict__ x, const float* __restrict__ W) {
    extern __shared__ __align__(16) char smraw[];
    const int i = blockIdx.x;
    const int t = threadIdx.x;
    const int w = t >> 5, L = t & 31;

    // ---- stage W_i (1024 rows x 16 c) fp32->fp16 ----
    const float4* Wg = reinterpret_cast<const float4*>(W);
    #pragma unroll
    for (int k = 0; k < 16; k++) {
        int v = t + 256 * k;
        int row = v >> 2, ch = v & 3;  // row = j*32+d
        float4 f = Wg[(size_t)((row >> 5) * II + i) * 128 + (row & 31) * 4 + ch];
        __half2* p = reinterpret_cast<__half2*>(smraw + SW_OFF + row * 48 + ch * 8);
        p[0] = __floats2half2_rn(f.x, f.y);
        p[1] = __floats2half2_rn(f.z, f.w);
    }
    // ---- stage x_i (64 b x 16 c) fp32->fp16 ----
    {
        int b = t >> 2, ch = t & 3;
        float4 f = reinterpret_cast<const float4*>(x)[(size_t)(b * II + i) * 4 + ch];
        __half2* p = reinterpret_cast<__half2*>(smraw + SX_OFF + b * 48 + ch * 8);
        p[0] = __floats2half2_rn(f.x, f.y);
        p[1] = __floats2half2_rn(f.z, f.w);
    }
    __syncthreads();

    const unsigned sbase = (unsigned)__cvta_generic_to_shared(smraw);

    // ---- B fragments: all 8 col-tiles (b 0..63), loaded once per warp ----
    u32 bf[8][2];
    {
        const unsigned xb = sbase + SX_OFF + ((L & 8) ? 16u : 0u) + (L & 7) * 48u;
        #pragma unroll
        for (int ct = 0; ct < 8; ct++) ldmx2(bf[ct][0], bf[ct][1], xb + ct * 8 * 48u);
    }

    const unsigned abase =
        sbase + SW_OFF + (L & 15) * 48u + ((L & 16) ? 16u : 0u);
    const unsigned stg = sbase + STG_OFF + w * STG_WARP +
                         (L & 7) * 48u + ((L & 8) ? 16u : 0u);
    char* gout = reinterpret_cast<char*>(g_U) + (size_t)i * 2048;

    #pragma unroll
    for (int rr = 0; rr < 8; rr++) {
        const int rt = w * 8 + rr;  // rows 16rt..16rt+15
        u32 a0, a1, a2, a3;
        ldmx4(a0, a1, a2, a3, abase + (unsigned)(16 * rt) * 48u);
        #pragma unroll
        for (int ct = 0; ct < 8; ct++) {
            float d0, d1, d2, d3;
            mma16816(d0, d1, d2, d3, a0, a1, a2, a3, bf[ct][0], bf[ct][1]);
            stmx2t(stg + ct * 8 * 48u, cvtpack(d0, d1), cvtpack(d2, d3));
        }
        __syncwarp();
        // readback (b-major, 32B per b) -> coalesced global STG.128
        #pragma unroll
        for (int rnd = 0; rnd < 4; rnd++) {
            int b = rnd * 16 + (L >> 1), h = L & 1;
            uint4 v = *reinterpret_cast<const uint4*>(
                smraw + STG_OFF + w * STG_WARP + b * 48 + h * 16);
            *reinterpret_cast<uint4*>(gout + ((size_t)b * II) * 2048 + rt * 32 +
                                      h * 16) = v;
        }
        __syncwarp();
    }
}

// ---------------------------------------------------------------------------
// Route compute step: lane l chunk m (uint4 = 8 halfs) holds j = 8m + (l>>2),
// d-seg (l&3)*8..+7. Logit reduce over 4-lane groups; softmax over 32 j via
// in-thread + xor 4,8,16. (Round-9, unchanged.)
// ---------------------------------------------------------------------------
__device__ __forceinline__ void cvt8(const uint4& r, float* uf) {
    const __half2* h = reinterpret_cast<const __half2*>(&r);
    #pragma unroll
    for (int p = 0; p < 4; p++) {
        float2 f = __half22float2(h[p]);
        uf[2 * p] = f.x;
        uf[2 * p + 1] = f.y;
    }
}

template <int MODE>
__device__ __forceinline__ void route_step(const uint4* r, const float ov[4][8],
                                           float sacc[4][8]) {
    float uf[4][8];
    #pragma unroll
    for (int m = 0; m < 4; m++) cvt8(r[m], uf[m]);
    float c[4];
    if (MODE == 0) {
        #pragma unroll
        for (int m = 0; m < 4; m++) c[m] = 0.03125f;
    } else {
        float tp[4];
        #pragma unroll
        for (int m = 0; m < 4; m++) {
            float a = uf[m][0] * ov[m][0];
            #pragma unroll
            for (int k = 1; k < 8; k++) a = fmaf(uf[m][k], ov[m][k], a);
            tp[m] = a;
        }
        #pragma unroll
        for (int s = 1; s < 4; s <<= 1)
            #pragma unroll
            for (int m = 0; m < 4; m++)
                tp[m] += __shfl_xor_sync(0xffffffffu, tp[m], s);
        float e[4], ss = 0.f;
        #pragma unroll
        for (int m = 0; m < 4; m++) {
            e[m] = __expf(tp[m]);
            ss += e[m];
        }
        ss += __shfl_xor_sync(0xffffffffu, ss, 4);
        ss += __shfl_xor_sync(0xffffffffu, ss, 8);
        ss += __shfl_xor_sync(0xffffffffu, ss, 16);
        float inv = __fdividef(1.0f, ss);
        #pragma unroll
        for (int m = 0; m < 4; m++) c[m] = e[m] * inv;
    }
    #pragma unroll
    for (int m = 0; m < 4; m++)
        #pragma unroll
        for (int k = 0; k < 8; k++) sacc[m][k] = fmaf(c[m], uf[m][k], sacc[m][k]);
}

// ---------------------------------------------------------------------------
// Kernel B: one routing pass, 5-stage block-wide cp.async ring (round-9).
// ---------------------------------------------------------------------------
template <int MODE, int DIR>
__global__ void __launch_bounds__(256, 2) route_kernel() {
    extern __shared__ __align__(16) char dsm[];
    __half* sU = reinterpret_cast<__half*>(dsm);                  // NSTAGE*16KB
    float* sS = reinterpret_cast<float*>(dsm + NSTAGE * 16384);   // 8*1024 f

    const int itile = DIR ? (NTILE - 1 - (int)blockIdx.x) : (int)blockIdx.x;
    const int b = DIR ? (BB - 1 - (int)blockIdx.y) : (int)blockIdx.y;
    const int t = threadIdx.x, w = t >> 5, l = t & 31;

    float ov[4][8];
    if (MODE > 0) {
        const float4* op = reinterpret_cast<const float4*>(g_osum + b * (JJ * DD));
        #pragma unroll
        for (int m = 0; m < 4; m++) {
            float4 f0 = op[m * 64 + 2 * l], f1 = op[m * 64 + 2 * l + 1];
            ov[m][0] = f0.x; ov[m][1] = f0.y; ov[m][2] = f0.z; ov[m][3] = f0.w;
            ov[m][4] = f1.x; ov[m][5] = f1.y; ov[m][6] = f1.z; ov[m][7] = f1.w;
        }
    }
    float sacc[4][8];
    #pragma unroll
    for (int m = 0; m < 4; m++)
        #pragma unroll
        for (int k = 0; k < 8; k++) sacc[m][k] = 0.f;

    const char* gbt = reinterpret_cast<const char*>(g_U) +
                      ((size_t)b * II + itile * 128) * 2048 + (size_t)t * 16;
    const unsigned su_base =
        (unsigned)__cvta_generic_to_shared(sU) + (unsigned)(t * 16);

    #pragma unroll
    for (int s = 0; s < NSTAGE - 1; s++) {
        #pragma unroll
        for (int k = 0; k < 4; k++)
            cpasync16(su_base + (unsigned)(s * 16384 + k * 4096),
                      gbt + (size_t)s * 16384 + k * 4096);
        cpcommit();
    }

    int rd = 0;
    int wr = NSTAGE - 1;
    for (int it = 0; it < NITER; it++) {
        cpwait<NSTAGE - 2>();
        __syncthreads();
        const uint4* p =
            reinterpret_cast<const uint4*>(sU + rd * 8192 + w * 1024);
        uint4 r[4];
        #pragma unroll
        for (int m = 0; m < 4; m++) r[m] = p[m * 32 + l];
        route_step<MODE>(r, ov, sacc);
        __syncthreads();
        {
            int s = it + NSTAGE - 1;
            if (s < NITER) {
                #pragma unroll
                for (int k = 0; k < 4; k++)
                    cpasync16(su_base + (unsigned)(wr * 16384 + k * 4096),
                              gbt + (size_t)s * 16384 + k * 4096);
            }
            cpcommit();
        }
        if (++rd == NSTAGE) rd = 0;
        if (++wr == NSTAGE) wr = 0;
    }

    float4* sp = reinterpret_cast<float4*>(sS + w * 1024);
    #pragma unroll
    for (int m = 0; m < 4; m++) {
        sp[(m * 32 + l) * 2 + 0] =
            make_float4(sacc[m][0], sacc[m][1], sacc[m][2], sacc[m][3]);
        sp[(m * 32 + l) * 2 + 1] =
            make_float4(sacc[m][4], sacc[m][5], sacc[m][6], sacc[m][7]);
    }
    __syncthreads();
    for (int idx = t; idx < JJ * DD; idx += 256) {
        float v = 0.f;
        #pragma unroll
        for (int ww = 0; ww < 8; ww++) v += sS[ww * 1024 + idx];
        g_spart[itile][b * (JJ * DD) + idx] = v;
    }
}

// ---------------------------------------------------------------------------
// Kernel C: reduce itile partials, squash, update osum / write final out.
// ---------------------------------------------------------------------------
__global__ void __launch_bounds__(256) squash_kernel(float* __restrict__ out,
                                                     int mode) {
    const int t = threadIdx.x;
    const int bj = blockIdx.x * 8 + (t >> 5);
    const int l = t & 31;
    float v = 0.f;
    #pragma unroll
    for (int it = 0; it < NTILE; it++) v += g_spart[it][bj * DD + l];
    float s2 = v * v;
    #pragma unroll
    for (int s = 1; s < 32; s <<= 1) s2 += __shfl_xor_sync(0xffffffffu, s2, s);
    float scale = (s2 / (1.0f + s2)) * rsqrtf(s2 + 1e-7f);
    float o = scale * v;
    if (mode == 2)
        out[bj * DD + l] = o;
    else if (mode == 1)
        g_osum[bj * DD + l] += o;
    else
        g_osum[bj * DD + l] = o;
}

// ---------------------------------------------------------------------------
extern "C" void kernel_launch(void* const* d_in, const int* in_sizes, int n_in,
                              void* d_out, int out_size) {
    const float* x;
    const float* W;
    if (in_sizes[0] == BB * II * CC) {
        x = (const float*)d_in[0];
        W = (const float*)d_in[1];
    } else {
        x = (const float*)d_in[1];
        W = (const float*)d_in[0];
    }

    const int uhat_smem = UHAT_SMEM;                                       // 76800
    const int route_smem = NSTAGE * 16384 + 8 * 1024 * (int)sizeof(float); // 114688
    cudaFuncSetAttribute(uhat_kernel, cudaFuncAttributeMaxDynamicSharedMemorySize,
                         uhat_smem);
    cudaFuncSetAttribute(route_kernel<0, 1>,
                         cudaFuncAttributeMaxDynamicSharedMemorySize, route_smem);
    cudaFuncSetAttribute(route_kernel<1, 0>,
                         cudaFuncAttributeMaxDynamicSharedMemorySize, route_smem);
    cudaFuncSetAttribute(route_kernel<2, 1>,
                         cudaFuncAttributeMaxDynamicSharedMemorySize, route_smem);

    float* out = (float*)d_out;
    uhat_kernel<<<II, 256, uhat_smem>>>(x, W);
    route_kernel<0, 1><<<dim3(NTILE, BB), 256, route_smem>>>();
    squash_kernel<<<BB * JJ / 8, 256>>>(out, 0);
    route_kernel<1, 0><<<dim3(NTILE, BB), 256, route_smem>>>();
    squash_kernel<<<BB * JJ / 8, 256>>>(out, 1);
    route_kernel<2, 1><<<dim3(NTILE, BB), 256, route_smem>>>();
    squash_kernel<<<BB * JJ / 8, 256>>>(out, 2);
}